// round 17
// baseline (speedup 1.0000x reference)
#include <cuda_runtime.h>
#include <cuda_bf16.h>
#include <cstdint>

#define BB 32
#define TT 256
#define DD 512
#define PP 20
#define EPSV 1e-12f

// ---------------- scratch (__device__ globals; no cudaMalloc allowed) ------
__device__ __align__(16) __nv_bfloat16 g_nbn_bf [BB * TT * DD];   // [b][t][d]
__device__ __align__(16) __nv_bfloat16 g_nbnT_bf[BB * DD * TT];   // [b][d][t]
__device__ __align__(16) __nv_bfloat16 g_nanT_bf[BB * DD * TT];   // [b][d][t]
__device__ __align__(16) __nv_bfloat16 g_alphaTb[(size_t)BB * DD * DD]; // [b][e][d]
__device__ __align__(16) float g_colpart[BB * 4 * DD];            // per (b, mtile, e)
__device__ __align__(16) __nv_bfloat16 g_hmean_bf[BB * TT * DD];  // [b][t][e]
__device__ __align__(16) __nv_bfloat16 g_W2bf[24 * 520];          // W^2, padded

__device__ __forceinline__ uint32_t smem_u32(const void* p) {
    return (uint32_t)__cvta_generic_to_shared(p);
}
// pack two fp32 -> bf16x2 (lo = x, hi = y), round-to-nearest-even
__device__ __forceinline__ uint32_t pack_bf2(float x, float y) {
    uint32_t r;
    asm("cvt.rn.bf16x2.f32 %0, %1, %2;" : "=r"(r) : "f"(y), "f"(x));
    return r;
}

// ---------------------------------------------------------------------------
// Kernel 1: row l2-normalize + transpose, bf16 outputs.
// ---------------------------------------------------------------------------
__global__ void __launch_bounds__(256) k_normT(const float* __restrict__ a,
                                               const float* __restrict__ b) {
    __shared__ float s[16 * 513];
    __shared__ float sinv[16];
    int which = blockIdx.z;
    int bb = blockIdx.y;
    int t0 = blockIdx.x * 16;
    const float* src = (which ? b : a) + ((size_t)bb * TT + t0) * DD;
    int tid = threadIdx.x;

#pragma unroll
    for (int i = 0; i < 8; i++) {
        int idx = tid + i * 256;
        int r = idx >> 7, c4 = idx & 127;
        float4 v = *(const float4*)(src + (size_t)r * DD + c4 * 4);
        float* sr = s + r * 513 + c4 * 4;
        sr[0] = v.x; sr[1] = v.y; sr[2] = v.z; sr[3] = v.w;
    }
    __syncthreads();

    int wid = tid >> 5, lid = tid & 31;
#pragma unroll
    for (int rr = 0; rr < 2; rr++) {
        int r = wid * 2 + rr;
        float ss = 0.f;
#pragma unroll
        for (int j = 0; j < 16; j++) { float v = s[r * 513 + lid + 32 * j]; ss += v * v; }
#pragma unroll
        for (int o = 16; o > 0; o >>= 1) ss += __shfl_xor_sync(0xffffffffu, ss, o);
        if (lid == 0) sinv[r] = rsqrtf(fmaxf(ss, EPSV));
    }
    __syncthreads();

    __nv_bfloat16* dstT = (which ? g_nbnT_bf : g_nanT_bf) + (size_t)bb * DD * TT;
#pragma unroll
    for (int i = 0; i < 8; i++) {
        int idx = tid + i * 256;
        int d = idx >> 2, jq = (idx & 3) * 4;
        float o0 = s[(jq + 0) * 513 + d] * sinv[jq + 0];
        float o1 = s[(jq + 1) * 513 + d] * sinv[jq + 1];
        float o2 = s[(jq + 2) * 513 + d] * sinv[jq + 2];
        float o3 = s[(jq + 3) * 513 + d] * sinv[jq + 3];
        uint2 u = make_uint2(pack_bf2(o0, o1), pack_bf2(o2, o3));
        *(uint2*)(dstT + (size_t)d * TT + t0 + jq) = u;
    }
    if (which) {
        __nv_bfloat16* dst = g_nbn_bf + ((size_t)bb * TT + t0) * DD;
#pragma unroll
        for (int i = 0; i < 8; i++) {
            int idx = tid + i * 256;
            int r = idx >> 7, c4 = idx & 127;
            float inv = sinv[r];
            float* sr = s + r * 513 + c4 * 4;
            uint2 u = make_uint2(pack_bf2(sr[0] * inv, sr[1] * inv),
                                 pack_bf2(sr[2] * inv, sr[3] * inv));
            *(uint2*)(dst + (size_t)r * DD + c4 * 4) = u;
        }
    }
}

// ---------------------------------------------------------------------------
// bf16 mma.sync GEMM, 4-stage cp.async pipeline, one barrier per K-chunk.
// CTA tile 128x128, K-chunk 32. Store transposed: C[n*512 + m], bf16.
// mode 1 (GEMM1): also emit per-CTA column sum-of-squares partials
// mode 2 (GEMM2): scale output by rsqrt(max(sum_j colpart[j][m], eps))
// ---------------------------------------------------------------------------
__global__ void __launch_bounds__(256, 2) k_gemm_bf16(
    const __nv_bfloat16* __restrict__ Ag, int lda, size_t strideA,
    const __nv_bfloat16* __restrict__ Bg, int ldb, size_t strideB,
    __nv_bfloat16* __restrict__ Cg, size_t strideC,
    float* __restrict__ colpart, int Ktot, int mode) {
    __shared__ __align__(16) char sm[4 * 16384];  // 64KB

    int b = blockIdx.z;
    int m0 = blockIdx.x * 128, n0 = blockIdx.y * 128;
    const __nv_bfloat16* A  = Ag + (size_t)b * strideA + (size_t)m0 * lda;
    const __nv_bfloat16* Bp = Bg + (size_t)b * strideB + (size_t)n0 * ldb;

    int tid = threadIdx.x, lane = tid & 31, wid = tid >> 5;
    int wm = wid & 1, wn = wid >> 1;
    uint32_t smbase = smem_u32(sm);

    float acc[4][4][4];
#pragma unroll
    for (int i = 0; i < 4; i++)
#pragma unroll
        for (int j = 0; j < 4; j++)
#pragma unroll
            for (int k = 0; k < 4; k++) acc[i][j][k] = 0.f;

    int nkt = Ktot / 32;

    auto issue_chunk = [&](int kt) {
        uint32_t base = smbase + (uint32_t)(kt & 3) * 16384u;
        int k0 = kt * 32;
#pragma unroll
        for (int i = 0; i < 2; i++) {
            int idx = tid + i * 256;
            int r = idx >> 2, q = idx & 3;
            uint32_t off = (uint32_t)(r * 64 + ((q ^ ((r >> 1) & 3)) << 4));
            const __nv_bfloat16* srcA = A + (size_t)r * lda + k0 + q * 8;
            asm volatile("cp.async.cg.shared.global [%0], [%1], 16;"
                         :: "r"(base + off), "l"(srcA));
            const __nv_bfloat16* srcB = Bp + (size_t)r * ldb + k0 + q * 8;
            asm volatile("cp.async.cg.shared.global [%0], [%1], 16;"
                         :: "r"(base + 8192u + off), "l"(srcB));
        }
        asm volatile("cp.async.commit_group;");
    };

    issue_chunk(0);
    issue_chunk(1);
    issue_chunk(2);

    for (int kt = 0; kt < nkt; kt++) {
        asm volatile("cp.async.wait_group 2;" ::: "memory");
        __syncthreads();
        if (kt + 3 < nkt) issue_chunk(kt + 3);

        uint32_t baseA = smbase + (uint32_t)(kt & 3) * 16384u;
        uint32_t baseB = baseA + 8192u;

#pragma unroll
        for (int ks = 0; ks < 2; ks++) {
            uint32_t af[4][4], bf[4][2];
#pragma unroll
            for (int mt = 0; mt < 4; mt++) {
                int r = wm * 64 + mt * 16 + (lane & 15);
                int q = ks * 2 + (lane >> 4);
                uint32_t addr = baseA + (uint32_t)(r * 64 + ((q ^ ((r >> 1) & 3)) << 4));
                asm volatile("ldmatrix.sync.aligned.m8n8.x4.shared.b16 {%0,%1,%2,%3}, [%4];"
                             : "=r"(af[mt][0]), "=r"(af[mt][1]),
                               "=r"(af[mt][2]), "=r"(af[mt][3])
                             : "r"(addr));
            }
#pragma unroll
            for (int nt = 0; nt < 4; nt++) {
                int r = wn * 32 + nt * 8 + (lane & 7);
                int q = ks * 2 + ((lane >> 3) & 1);
                uint32_t addr = baseB + (uint32_t)(r * 64 + ((q ^ ((r >> 1) & 3)) << 4));
                asm volatile("ldmatrix.sync.aligned.m8n8.x2.shared.b16 {%0,%1}, [%2];"
                             : "=r"(bf[nt][0]), "=r"(bf[nt][1])
                             : "r"(addr));
            }
#pragma unroll
            for (int mt = 0; mt < 4; mt++)
#pragma unroll
                for (int nt = 0; nt < 4; nt++) {
                    asm volatile(
                        "mma.sync.aligned.m16n8k16.row.col.f32.bf16.bf16.f32 "
                        "{%0,%1,%2,%3}, {%4,%5,%6,%7}, {%8,%9}, {%0,%1,%2,%3};"
                        : "+f"(acc[mt][nt][0]), "+f"(acc[mt][nt][1]),
                          "+f"(acc[mt][nt][2]), "+f"(acc[mt][nt][3])
                        : "r"(af[mt][0]), "r"(af[mt][1]),
                          "r"(af[mt][2]), "r"(af[mt][3]),
                          "r"(bf[nt][0]), "r"(bf[nt][1]));
                }
        }
    }

    // ---- epilogue ----
    __nv_bfloat16* Cb = Cg + (size_t)b * strideC;

    if (mode == 1) {
#pragma unroll
        for (int mt = 0; mt < 4; mt++) {
            int r0 = m0 + wm * 64 + mt * 16 + (lane >> 2);
#pragma unroll
            for (int nt = 0; nt < 4; nt++) {
                int c0 = n0 + wn * 32 + nt * 8 + (lane & 3) * 2;
                Cb[(size_t)c0 * 512 + r0]           = __float2bfloat16(acc[mt][nt][0]);
                Cb[(size_t)(c0 + 1) * 512 + r0]     = __float2bfloat16(acc[mt][nt][1]);
                Cb[(size_t)c0 * 512 + r0 + 8]       = __float2bfloat16(acc[mt][nt][2]);
                Cb[(size_t)(c0 + 1) * 512 + r0 + 8] = __float2bfloat16(acc[mt][nt][3]);
            }
        }
        float p0[4], p1[4];
#pragma unroll
        for (int nt = 0; nt < 4; nt++) {
            float s0 = 0.f, s1 = 0.f;
#pragma unroll
            for (int mt = 0; mt < 4; mt++) {
                s0 += acc[mt][nt][0] * acc[mt][nt][0] + acc[mt][nt][2] * acc[mt][nt][2];
                s1 += acc[mt][nt][1] * acc[mt][nt][1] + acc[mt][nt][3] * acc[mt][nt][3];
            }
#pragma unroll
            for (int o = 4; o < 32; o <<= 1) {
                s0 += __shfl_xor_sync(0xffffffffu, s0, o);
                s1 += __shfl_xor_sync(0xffffffffu, s1, o);
            }
            p0[nt] = s0; p1[nt] = s1;
        }
        __syncthreads();
        float* psum = (float*)sm;
        if (wm == 0 && lane < 4) {
#pragma unroll
            for (int nt = 0; nt < 4; nt++) {
                int idx = wn * 32 + nt * 8 + lane * 2;
                psum[idx] = p0[nt]; psum[idx + 1] = p1[nt];
            }
        }
        __syncthreads();
        if (wm == 1 && lane < 4) {
#pragma unroll
            for (int nt = 0; nt < 4; nt++) {
                int idx = wn * 32 + nt * 8 + lane * 2;
                psum[idx] += p0[nt]; psum[idx + 1] += p1[nt];
            }
        }
        __syncthreads();
        if (tid < 128)
            colpart[((size_t)b * 4 + blockIdx.x) * DD + n0 + tid] = psum[tid];
    } else {
        const float* cp = colpart + (size_t)b * 4 * DD;
#pragma unroll
        for (int mt = 0; mt < 4; mt++) {
            int r0 = m0 + wm * 64 + mt * 16 + (lane >> 2);
            float cs0 = cp[r0] + cp[DD + r0] + cp[2 * DD + r0] + cp[3 * DD + r0];
            float cs1 = cp[r0 + 8] + cp[DD + r0 + 8] + cp[2 * DD + r0 + 8] + cp[3 * DD + r0 + 8];
            float sc0 = rsqrtf(fmaxf(cs0, EPSV));
            float sc1 = rsqrtf(fmaxf(cs1, EPSV));
#pragma unroll
            for (int nt = 0; nt < 4; nt++) {
                int c0 = n0 + wn * 32 + nt * 8 + (lane & 3) * 2;
                Cb[(size_t)c0 * 512 + r0]           = __float2bfloat16(acc[mt][nt][0] * sc0);
                Cb[(size_t)(c0 + 1) * 512 + r0]     = __float2bfloat16(acc[mt][nt][1] * sc0);
                Cb[(size_t)c0 * 512 + r0 + 8]       = __float2bfloat16(acc[mt][nt][2] * sc1);
                Cb[(size_t)(c0 + 1) * 512 + r0 + 8] = __float2bfloat16(acc[mt][nt][3] * sc1);
            }
        }
    }
}

// ---------------------------------------------------------------------------
// W^2 prepack: g_W2bf[24][520] bf16, zero-padded beyond (20, 512).
// ---------------------------------------------------------------------------
__global__ void k_w2(const float* __restrict__ W) {
    int i = blockIdx.x * blockDim.x + threadIdx.x;
    if (i >= 24 * 520) return;
    int p = i / 520, d = i - p * 520;
    float v = 0.f;
    if (p < PP && d < DD) { float w = W[p * DD + d]; v = w * w; }
    g_W2bf[i] = __float2bfloat16(v);
}

// ---------------------------------------------------------------------------
// Perspective via tensor cores, register-direct A fragments, K-split x4.
// 128 thr / 4 warps per block, 16 rows. Warp wk handles K range [wk*128,
// wk*128+128). Warps 1-3 dump 36-float partials to padded smem (stride 37,
// conflict-free); warp 0 adds all and writes output. Grid = 512 CTAs.
// ---------------------------------------------------------------------------
__global__ void __launch_bounds__(128) k_persp4(const float* __restrict__ inp_a,
                                                float* __restrict__ out, int dup) {
    __shared__ __align__(16) __nv_bfloat16 sW2[24 * 520];   // 24.4KB
    __shared__ __align__(16) float sred[3 * 32 * 37];       // 14.2KB

    int tid = threadIdx.x, lane = tid & 31, wk = tid >> 5;
    int row0 = blockIdx.x * 16;

    for (int i = tid; i < 24 * 520 / 8; i += 128)
        ((uint4*)sW2)[i] = ((const uint4*)g_W2bf)[i];
    __syncthreads();
    uint32_t w2base = smem_u32(sW2);

    int r = lane >> 2, c = (lane & 3) * 2;
    int R = row0 + r;                          // rows R, R+8
    const float* a0p = inp_a + (size_t)R * DD;
    const float* a1p = inp_a + (size_t)(R + 8) * DD;
    const __nv_bfloat16* h0p = g_hmean_bf + (size_t)R * DD;
    const __nv_bfloat16* h1p = g_hmean_bf + (size_t)(R + 8) * DD;

    float acc[3][3][4];
#pragma unroll
    for (int i = 0; i < 3; i++)
#pragma unroll
        for (int j = 0; j < 3; j++)
#pragma unroll
            for (int k = 0; k < 4; k++) acc[i][j][k] = 0.f;

    int kbase = wk * 128;
#pragma unroll
    for (int kt = 0; kt < 8; kt++) {           // K-steps of 16 within quarter
        int k0 = kbase + kt * 16;
        float2 aA = *(const float2*)(a0p + k0 + c);
        float2 aB = *(const float2*)(a1p + k0 + c);
        float2 aC = *(const float2*)(a0p + k0 + c + 8);
        float2 aD = *(const float2*)(a1p + k0 + c + 8);
        uint32_t hAu = *(const uint32_t*)(h0p + k0 + c);
        uint32_t hBu = *(const uint32_t*)(h1p + k0 + c);
        uint32_t hCu = *(const uint32_t*)(h0p + k0 + c + 8);
        uint32_t hDu = *(const uint32_t*)(h1p + k0 + c + 8);
        float2 hA = __bfloat1622float2(*(__nv_bfloat162*)&hAu);
        float2 hB = __bfloat1622float2(*(__nv_bfloat162*)&hBu);
        float2 hC = __bfloat1622float2(*(__nv_bfloat162*)&hCu);
        float2 hD = __bfloat1622float2(*(__nv_bfloat162*)&hDu);

        uint32_t f[3][4];
        f[0][0] = pack_bf2(aA.x * aA.x, aA.y * aA.y);
        f[0][1] = pack_bf2(aB.x * aB.x, aB.y * aB.y);
        f[0][2] = pack_bf2(aC.x * aC.x, aC.y * aC.y);
        f[0][3] = pack_bf2(aD.x * aD.x, aD.y * aD.y);
        f[1][0] = pack_bf2(hA.x * hA.x, hA.y * hA.y);
        f[1][1] = pack_bf2(hB.x * hB.x, hB.y * hB.y);
        f[1][2] = pack_bf2(hC.x * hC.x, hC.y * hC.y);
        f[1][3] = pack_bf2(hD.x * hD.x, hD.y * hD.y);
        f[2][0] = pack_bf2(aA.x * hA.x, aA.y * hA.y);
        f[2][1] = pack_bf2(aB.x * hB.x, aB.y * hB.y);
        f[2][2] = pack_bf2(aC.x * hC.x, aC.y * hC.y);
        f[2][3] = pack_bf2(aD.x * hD.x, aD.y * hD.y);

        uint32_t bfr[3][2];
#pragma unroll
        for (int nt = 0; nt < 3; nt++) {
            int br = nt * 8 + (lane & 7);
            int bk = k0 + ((lane >> 3) & 1) * 8;
            uint32_t addr = w2base + (uint32_t)(br * 1040 + bk * 2);
            asm volatile("ldmatrix.sync.aligned.m8n8.x2.shared.b16 {%0,%1}, [%2];"
                         : "=r"(bfr[nt][0]), "=r"(bfr[nt][1])
                         : "r"(addr));
        }
#pragma unroll
        for (int s = 0; s < 3; s++)
#pragma unroll
            for (int nt = 0; nt < 3; nt++) {
                asm volatile(
                    "mma.sync.aligned.m16n8k16.row.col.f32.bf16.bf16.f32 "
                    "{%0,%1,%2,%3}, {%4,%5,%6,%7}, {%8,%9}, {%0,%1,%2,%3};"
                    : "+f"(acc[s][nt][0]), "+f"(acc[s][nt][1]),
                      "+f"(acc[s][nt][2]), "+f"(acc[s][nt][3])
                    : "r"(f[s][0]), "r"(f[s][1]), "r"(f[s][2]), "r"(f[s][3]),
                      "r"(bfr[nt][0]), "r"(bfr[nt][1]));
            }
    }

    // ---- cross-K reduction: warps 1..3 dump, warp 0 adds ----
    __syncthreads();
    if (wk > 0) {
        float* dst = sred + ((wk - 1) * 32 + lane) * 37;
#pragma unroll
        for (int s = 0; s < 3; s++)
#pragma unroll
            for (int nt = 0; nt < 3; nt++)
#pragma unroll
                for (int k = 0; k < 4; k++)
                    dst[s * 12 + nt * 4 + k] = acc[s][nt][k];
    }
    __syncthreads();
    if (wk == 0) {
#pragma unroll
        for (int j = 0; j < 3; j++) {
            const float* src = sred + (j * 32 + lane) * 37;
#pragma unroll
            for (int s = 0; s < 3; s++)
#pragma unroll
                for (int nt = 0; nt < 3; nt++)
#pragma unroll
                    for (int k = 0; k < 4; k++)
                        acc[s][nt][k] += src[s * 12 + nt * 4 + k];
        }

        // ---- epilogue ----
        int rg0 = row0 + (lane >> 2);
#pragma unroll
        for (int nt = 0; nt < 3; nt++) {
            int c0 = nt * 8 + (lane & 3) * 2;
#pragma unroll
            for (int half = 0; half < 2; half++) {
                int rg = rg0 + half * 8;
                float s1a = acc[0][nt][half * 2],     s1b = acc[0][nt][half * 2 + 1];
                float s2a = acc[1][nt][half * 2],     s2b = acc[1][nt][half * 2 + 1];
                float s3a = acc[2][nt][half * 2],     s3b = acc[2][nt][half * 2 + 1];
                float va = s3a * rsqrtf(fmaxf(s1a, EPSV)) * rsqrtf(fmaxf(s2a, EPSV));
                float vb = s3b * rsqrtf(fmaxf(s1b, EPSV)) * rsqrtf(fmaxf(s2b, EPSV));
                if (c0 < PP) {
                    out[(size_t)rg * PP + c0] = va;
                    if (dup) out[(size_t)BB * TT * PP + (size_t)rg * PP + c0] = va;
                }
                if (c0 + 1 < PP) {
                    out[(size_t)rg * PP + c0 + 1] = vb;
                    if (dup) out[(size_t)BB * TT * PP + (size_t)rg * PP + c0 + 1] = vb;
                }
            }
        }
    }
}

// ---------------------------------------------------------------------------
extern "C" void kernel_launch(void* const* d_in, const int* in_sizes, int n_in,
                              void* d_out, int out_size) {
    const float* inp_a = (const float*)d_in[0];
    const float* inp_b = (const float*)d_in[1];
    const float* W     = (const float*)d_in[2];
    float* out = (float*)d_out;
    int dup = (out_size >= 2 * BB * TT * PP) ? 1 : 0;

    void *p_nbn_bf, *p_nbnT_bf, *p_nanT_bf, *p_alphaTb, *p_colpart, *p_hmean_bf;
    cudaGetSymbolAddress(&p_nbn_bf, g_nbn_bf);
    cudaGetSymbolAddress(&p_nbnT_bf, g_nbnT_bf);
    cudaGetSymbolAddress(&p_nanT_bf, g_nanT_bf);
    cudaGetSymbolAddress(&p_alphaTb, g_alphaTb);
    cudaGetSymbolAddress(&p_colpart, g_colpart);
    cudaGetSymbolAddress(&p_hmean_bf, g_hmean_bf);

    // 1) normalize + transpose -> bf16; W^2 prepack (tiny)
    k_w2<<<(24 * 520 + 255) / 256, 256>>>(W);
    k_normT<<<dim3(TT / 16, BB, 2), 256>>>(inp_a, inp_b);

    // 2) GEMM1: alphaTb[e][d] = bf16( sum_t nbnT[d,t]*nanT[e,t] ) + colpart sumsq
    k_gemm_bf16<<<dim3(4, 4, BB), 256>>>(
        (const __nv_bfloat16*)p_nbnT_bf, TT, (size_t)DD * TT,
        (const __nv_bfloat16*)p_nanT_bf, TT, (size_t)DD * TT,
        (__nv_bfloat16*)p_alphaTb, (size_t)DD * DD,
        (float*)p_colpart, TT, 1);

    // 3) GEMM2: hmean_bf[t][e] = bf16( (sum_d alphaTb[e,d]*nbn[t,d]) * invcol[e] )
    k_gemm_bf16<<<dim3(4, 2, BB), 256>>>(
        (const __nv_bfloat16*)p_alphaTb, DD, (size_t)DD * DD,
        (const __nv_bfloat16*)p_nbn_bf, DD, (size_t)TT * DD,
        (__nv_bfloat16*)p_hmean_bf, (size_t)TT * DD,
        (float*)p_colpart, DD, 2);

    // 4) perspective scores via tensor cores, K-split x4, grid 512
    k_persp4<<<BB * TT / 16, 128>>>(inp_a, out, dup);
}